// round 16
// baseline (speedup 1.0000x reference)
#include <cuda_runtime.h>
#include <math.h>
#include <stdint.h>

#define B 8
#define S 2048
#define I_IN 8
#define H 256
#define NC 16        // CTAs per batch
#define CHUNK 16     // h outputs per CTA
#define NT 256
#define NSPLIT 8
#define SC (S / NSPLIT)   // 256
#define CANARY 0x7FC00001u
#define GROWS (4 * H)     // 1024 gate rows
#define FULLM 0xffffffffu

// ---------------- device scratch ----------------
__device__ float g_hs0[(size_t)B * S * H];
__device__ float g_hs1[(size_t)B * S * H];
__device__ float g_xp [(size_t)B * S * GROWS];   // w_ih0.x + b_ih0 + b_hh0
__device__ float g_pm[B * 4 * NSPLIT];
__device__ float g_ps[B * 4 * NSPLIT];
__device__ float g_ph[B * 4 * NSPLIT * H];

// HW tanh (sm_75+)
__device__ __forceinline__ float ftanh_(float x) {
    float y; asm("tanh.approx.f32 %0, %1;" : "=f"(y) : "f"(x)); return y;
}
__device__ __forceinline__ float fsig_(float x) {
    return 0.5f * ftanh_(0.5f * x) + 0.5f;
}

__device__ __forceinline__ uint64_t fma2_(uint64_t a, uint64_t b, uint64_t c) {
    uint64_t d;
    asm("fma.rn.f32x2 %0, %1, %2, %3;" : "=l"(d) : "l"(a), "l"(b), "l"(c));
    return d;
}
__device__ __forceinline__ float hsum2_(uint64_t v) {
    return __uint_as_float((uint32_t)v) + __uint_as_float((uint32_t)(v >> 32));
}
__device__ __forceinline__ uint32_t ldg_relaxed_u32(const uint32_t* p) {
    uint32_t v;
    asm volatile("ld.relaxed.gpu.global.b32 %0, [%1];" : "=r"(v) : "l"(p) : "memory");
    return v;
}
__device__ __forceinline__ void stg_relaxed_u32(uint32_t* p, uint32_t v) {
    asm volatile("st.relaxed.gpu.global.b32 [%0], %1;" :: "l"(p), "r"(v) : "memory");
}

// ---------------- canary fill -----------------------------------------------------
__global__ void fill_kernel() {
    const uint4 c = make_uint4(CANARY, CANARY, CANARY, CANARY);
    const size_t n4 = (size_t)B * S * H / 4;
    uint4* p0 = reinterpret_cast<uint4*>(g_hs0);
    uint4* p1 = reinterpret_cast<uint4*>(g_hs1);
    for (size_t i = (size_t)blockIdx.x * blockDim.x + threadIdx.x; i < n4;
         i += (size_t)gridDim.x * blockDim.x) {
        p0[i] = c; p1[i] = c;
    }
}

// ---------------- x-projection precompute: xp = w_ih0 . x + b_ih0 + b_hh0 --------
__global__ void __launch_bounds__(256, 4) xproj_kernel(
    const float* __restrict__ xin, const float* __restrict__ w_ih0,
    const float* __restrict__ b_ih0, const float* __restrict__ b_hh0)
{
    const int t0 = blockIdx.x * 8;
    const int b  = blockIdx.y;
    const int tid = threadIdx.x;
    __shared__ float sx[8][I_IN];
    if (tid < 64) sx[tid >> 3][tid & 7] = xin[((size_t)b * S + t0 + (tid >> 3)) * I_IN + (tid & 7)];
    __syncthreads();
    float* xpb = g_xp + (size_t)b * S * GROWS;
#pragma unroll
    for (int rr = 0; rr < 4; rr++) {
        int row = rr * 256 + tid;
        float4 w0 = reinterpret_cast<const float4*>(w_ih0 + row * I_IN)[0];
        float4 w1 = reinterpret_cast<const float4*>(w_ih0 + row * I_IN)[1];
        float bias = b_ih0[row] + b_hh0[row];
#pragma unroll
        for (int ts = 0; ts < 8; ts++) {
            float v = bias
                + w0.x * sx[ts][0] + w0.y * sx[ts][1] + w0.z * sx[ts][2] + w0.w * sx[ts][3]
                + w1.x * sx[ts][4] + w1.y * sx[ts][5] + w1.z * sx[ts][6] + w1.w * sx[ts][7];
            xpb[(size_t)(t0 + ts) * GROWS + row] = v;
        }
    }
}

__global__ void dummy_kernel() {}

// ---------------- layer-0 LSTM: warp-local gates, 1 barrier/step ------------------
// Warp w owns h-outputs {2w, 2w+1} of the CTA chunk. Lane l: rw=l&7 selects the
// gate row (q=rw>>1, jj=rw&1), seg=l>>3 the 64-wide dot slice. Row totals by
// shfl_xor(8,16); activations in-lane; cell+publish in lanes 0-1.
__global__ void __launch_bounds__(NT, 1) lstm0_kernel(const float* __restrict__ w_hh0)
{
    const int r   = blockIdx.x;
    const int b   = blockIdx.y;
    const int tid = threadIdx.x;
    const int w   = tid >> 5;
    const int l   = tid & 31;
    const int rw  = l & 7;
    const int q   = rw >> 1;
    const int jj  = rw & 1;
    const int seg = l >> 3;
    const int row = q * H + r * CHUNK + 2 * w + jj;

    __shared__ alignas(16) float sh_h[2][H];

    uint64_t whh2[32];
    {
        const uint64_t* p = reinterpret_cast<const uint64_t*>(w_hh0) + ((row * H + seg * 64) >> 1);
#pragma unroll
        for (int k = 0; k < 32; k++) whh2[k] = p[k];
    }

    uint32_t* hs_u = reinterpret_cast<uint32_t*>(g_hs0) + (size_t)b * S * H;
    const float* xp_ptr = g_xp + (size_t)b * S * GROWS + row;
    float xpreg = __ldg(xp_ptr);                 // xp(0) incl. both biases

    sh_h[0][tid] = 0.f; sh_h[1][tid] = 0.f;
    __syncthreads();

    const bool self_word = (tid >= r * CHUNK) && (tid < r * CHUNK + CHUNK);
    float c = 0.f;   // cell state (lanes 0,1 of each warp)

    for (int t = 0; t < S; t++) {
        // poll h(t-1) into buffer t&1 (own chunk self-seeded last iteration)
        if (t > 0 && !self_word) {
            const uint32_t* p = hs_u + (size_t)(t - 1) * H + tid;
            uint32_t v = ldg_relaxed_u32(p);
            while (v == CANARY) v = ldg_relaxed_u32(p);
            sh_h[t & 1][tid] = __uint_as_float(v);
        }
        __syncthreads();                                   // single barrier

        // 64-wide dot slice
        const uint4* h128 = reinterpret_cast<const uint4*>(&sh_h[t & 1][seg * 64]);
        uint64_t a0 = 0, a1 = 0;
#pragma unroll
        for (int k = 0; k < 16; k++) {
            uint4 hv = h128[k];
            uint64_t lo = ((uint64_t)hv.y << 32) | hv.x;
            uint64_t hi = ((uint64_t)hv.w << 32) | hv.z;
            a0 = fma2_(whh2[2 * k], lo, a0);
            a1 = fma2_(whh2[2 * k + 1], hi, a1);
        }
        float v = hsum2_(a0) + hsum2_(a1);
        v += __shfl_xor_sync(FULLM, v, 8);
        v += __shfl_xor_sync(FULLM, v, 16);                // row total in all 4 copies
        v += xpreg;
        if (t + 1 < S) xpreg = __ldg(xp_ptr + (size_t)(t + 1) * GROWS);
        float act = (q == 2) ? ftanh_(v) : fsig_(v);
        // gather f,g,o for this warp's two h-outputs (lanes 0,1 consume)
        float fg = __shfl_sync(FULLM, act, 2 + (l & 1));
        float gv = __shfl_sync(FULLM, act, 4 + (l & 1));
        float og = __shfl_sync(FULLM, act, 6 + (l & 1));
        if (l < 2) {
            c = fg * c + act * gv;                         // act = i-gate (rw=l, q=0)
            float hnew = og * ftanh_(c);
            int hidx = r * CHUNK + 2 * w + l;
            sh_h[(t + 1) & 1][hidx] = hnew;                // self-seed next buffer
            stg_relaxed_u32(hs_u + (size_t)t * H + hidx, __float_as_uint(hnew));
        }
    }
}

// ---------------- layer-1 LSTM: same structure + wih dot over h0(t) ---------------
__global__ void __launch_bounds__(NT, 1) lstm1_kernel(
    const float* __restrict__ w_ih1, const float* __restrict__ w_hh1,
    const float* __restrict__ b_ih1, const float* __restrict__ b_hh1)
{
    const int r   = blockIdx.x;
    const int b   = blockIdx.y;
    const int tid = threadIdx.x;
    const int w   = tid >> 5;
    const int l   = tid & 31;
    const int rw  = l & 7;
    const int q   = rw >> 1;
    const int jj  = rw & 1;
    const int seg = l >> 3;
    const int row = q * H + r * CHUNK + 2 * w + jj;

    __shared__ alignas(16) float sh_h[2][H];
    __shared__ alignas(16) float sh_x[2][H];

    uint64_t whh2[32], wih2[32];
    {
        const uint64_t* p = reinterpret_cast<const uint64_t*>(w_hh1) + ((row * H + seg * 64) >> 1);
#pragma unroll
        for (int k = 0; k < 32; k++) whh2[k] = p[k];
    }
    {
        const uint64_t* p = reinterpret_cast<const uint64_t*>(w_ih1) + ((row * H + seg * 64) >> 1);
#pragma unroll
        for (int k = 0; k < 32; k++) wih2[k] = p[k];
    }
    const float bias = b_ih1[row] + b_hh1[row];

    const float* xb = g_hs0 + (size_t)b * S * H;           // complete at launch
    uint32_t* hs_u  = reinterpret_cast<uint32_t*>(g_hs1) + (size_t)b * S * H;

    sh_h[0][tid] = 0.f; sh_h[1][tid] = 0.f;
    float xreg = __ldg(xb + tid);                           // h0(0)
    __syncthreads();

    const bool self_word = (tid >= r * CHUNK) && (tid < r * CHUNK + CHUNK);
    float c = 0.f;

    for (int t = 0; t < S; t++) {
        // stage x(t) into buffer t&1; prefetch x(t+1)
        sh_x[t & 1][tid] = xreg;
        {
            int tn = (t + 1 < S) ? t + 1 : t;
            xreg = __ldg(xb + (size_t)tn * H + tid);
        }
        if (t > 0 && !self_word) {
            const uint32_t* p = hs_u + (size_t)(t - 1) * H + tid;
            uint32_t v = ldg_relaxed_u32(p);
            while (v == CANARY) v = ldg_relaxed_u32(p);
            sh_h[t & 1][tid] = __uint_as_float(v);
        }
        __syncthreads();                                   // single barrier

        const uint4* h128 = reinterpret_cast<const uint4*>(&sh_h[t & 1][seg * 64]);
        const uint4* x128 = reinterpret_cast<const uint4*>(&sh_x[t & 1][seg * 64]);
        uint64_t a0 = 0, a1 = 0;
#pragma unroll
        for (int k = 0; k < 16; k++) {
            uint4 hv = h128[k];
            uint64_t lo = ((uint64_t)hv.y << 32) | hv.x;
            uint64_t hi = ((uint64_t)hv.w << 32) | hv.z;
            a0 = fma2_(whh2[2 * k], lo, a0);
            a1 = fma2_(whh2[2 * k + 1], hi, a1);
        }
#pragma unroll
        for (int k = 0; k < 16; k++) {
            uint4 xv = x128[k];
            uint64_t lo = ((uint64_t)xv.y << 32) | xv.x;
            uint64_t hi = ((uint64_t)xv.w << 32) | xv.z;
            a0 = fma2_(wih2[2 * k], lo, a0);
            a1 = fma2_(wih2[2 * k + 1], hi, a1);
        }
        float v = hsum2_(a0) + hsum2_(a1);
        v += __shfl_xor_sync(FULLM, v, 8);
        v += __shfl_xor_sync(FULLM, v, 16);
        v += bias;
        float act = (q == 2) ? ftanh_(v) : fsig_(v);
        float fg = __shfl_sync(FULLM, act, 2 + (l & 1));
        float gv = __shfl_sync(FULLM, act, 4 + (l & 1));
        float og = __shfl_sync(FULLM, act, 6 + (l & 1));
        if (l < 2) {
            c = fg * c + act * gv;
            float hnew = og * ftanh_(c);
            int hidx = r * CHUNK + 2 * w + l;
            sh_h[(t + 1) & 1][hidx] = hnew;
            stg_relaxed_u32(hs_u + (size_t)t * H + hidx, __float_as_uint(hnew));
        }
    }
}

// ---------------- attention partials: split-S, split-softmax ---------------------
__global__ void __launch_bounds__(NT, 1) attn_part_kernel(
    const float* __restrict__ wq, const float* __restrict__ bq,
    const float* __restrict__ wk, const float* __restrict__ bk)
{
    const int cidx = blockIdx.x;
    const int bh   = blockIdx.y;
    const int b = bh >> 2, hd = bh & 3;
    const int tid = threadIdx.x;
    const float* h1b = g_hs1 + (size_t)b * S * H;
    const int base = cidx * SC;

    __shared__ float sh_last[H];
    __shared__ float sh_q[64];
    __shared__ float sh_qW[H];
    __shared__ float sh_qb;
    __shared__ float sc[SC];
    __shared__ float red[NT];

    sh_last[tid] = h1b[(size_t)(S - 1) * H + tid];
    __syncthreads();
    if (tid < 64) {
        int rq = hd * 64 + tid;
        float a = bq[rq];
#pragma unroll 4
        for (int k = 0; k < H; k++) a += wq[rq * H + k] * sh_last[k];
        sh_q[tid] = a;
    }
    __syncthreads();
    {
        float a = 0.f;
#pragma unroll 4
        for (int d = 0; d < 64; d++) a += sh_q[d] * wk[(hd * 64 + d) * H + tid];
        sh_qW[tid] = a;
    }
    if (tid == 0) {
        float a = 0.f;
        for (int d = 0; d < 64; d++) a += sh_q[d] * bk[hd * 64 + d];
        sh_qb = a;
    }
    __syncthreads();

    const float L2D = -0.07400058144377693f;   // log2(0.95)
    const int warp = tid >> 5, lane = tid & 31;
    float qr[8];
#pragma unroll
    for (int k = 0; k < 8; k++) qr[k] = sh_qW[lane * 8 + k];

#pragma unroll 2
    for (int i = warp; i < SC; i += 8) {
        int t = base + i;
        const float4* hr4 = reinterpret_cast<const float4*>(h1b + (size_t)t * H);
        float4 h0v = hr4[lane * 2], h1v = hr4[lane * 2 + 1];
        float a = qr[0]*h0v.x + qr[1]*h0v.y + qr[2]*h0v.z + qr[3]*h0v.w
                + qr[4]*h1v.x + qr[5]*h1v.y + qr[6]*h1v.z + qr[7]*h1v.w;
#pragma unroll
        for (int o = 16; o; o >>= 1) a += __shfl_xor_sync(0xffffffffu, a, o);
        if (lane == 0)
            sc[i] = (a + sh_qb) * 0.125f * exp2f((float)(S - 1 - t) * L2D);
    }
    __syncthreads();

    red[tid] = sc[tid]; __syncthreads();
    for (int o = NT / 2; o; o >>= 1) { if (tid < o) red[tid] = fmaxf(red[tid], red[tid + o]); __syncthreads(); }
    const float M = red[0]; __syncthreads();
    float e = expf(sc[tid] - M);
    sc[tid] = e;
    red[tid] = e; __syncthreads();
    for (int o = NT / 2; o; o >>= 1) { if (tid < o) red[tid] += red[tid + o]; __syncthreads(); }
    const float SUM = red[0];
    __syncthreads();

    float acc = 0.f;
#pragma unroll 8
    for (int i = 0; i < SC; i++) acc += sc[i] * h1b[(size_t)(base + i) * H + tid];
    g_ph[(size_t)(bh * NSPLIT + cidx) * H + tid] = acc;
    if (tid == 0) { g_pm[bh * NSPLIT + cidx] = M; g_ps[bh * NSPLIT + cidx] = SUM; }
}

// ---------------- tail: combine splits + V + O + heads (fused) -------------------
__global__ void __launch_bounds__(NT, 1) tail_kernel(
    const float* __restrict__ wv, const float* __restrict__ bv,
    const float* __restrict__ wo, const float* __restrict__ bo,
    const float* __restrict__ wm, const float* __restrict__ bm,
    const float* __restrict__ wvr, const float* __restrict__ bvr,
    float* __restrict__ out)
{
    const int b = blockIdx.x;
    const int tid = threadIdx.x;
    __shared__ float sh_w[NSPLIT];
    __shared__ float sh_hbar[H];
    __shared__ float sh_attn[H];
    __shared__ float sctx[H];
    __shared__ float sh_inv;

    for (int hd = 0; hd < 4; hd++) {
        const int bh = b * 4 + hd;
        if (tid == 0) {
            float M = -1e30f;
            for (int cI = 0; cI < NSPLIT; cI++) M = fmaxf(M, g_pm[bh * NSPLIT + cI]);
            float tot = 0.f;
            for (int cI = 0; cI < NSPLIT; cI++) {
                float w = expf(g_pm[bh * NSPLIT + cI] - M);
                sh_w[cI] = w;
                tot += w * g_ps[bh * NSPLIT + cI];
            }
            sh_inv = 1.f / tot;
        }
        __syncthreads();
        float a = 0.f;
#pragma unroll
        for (int cI = 0; cI < NSPLIT; cI++) a += sh_w[cI] * g_ph[(size_t)(bh * NSPLIT + cI) * H + tid];
        sh_hbar[tid] = a * sh_inv;
        __syncthreads();
        if (tid < 64) {
            int rv = hd * 64 + tid;
            float o = bv[rv];
#pragma unroll 4
            for (int k = 0; k < H; k++) o += wv[rv * H + k] * sh_hbar[k];
            sh_attn[hd * 64 + tid] = o;
        }
        __syncthreads();
    }

    float a = bo[tid];
#pragma unroll 4
    for (int k = 0; k < H; k++) a += wo[tid * H + k] * sh_attn[k];
    sctx[tid] = a;
    __syncthreads();
    if (tid < 5) {
        float m = bm[tid], lv = bvr[tid];
        for (int k = 0; k < H; k++) {
            m  += wm[tid * H + k] * sctx[k];
            lv += wvr[tid * H + k] * sctx[k];
        }
        out[b * 5 + tid] = m;
        out[B * 5 + b * 5 + tid] = lv;
    }
}

// ---------------- launch ----------------------------------------------------------
extern "C" void kernel_launch(void* const* d_in, const int* in_sizes, int n_in,
                              void* d_out, int out_size) {
    const float* x     = (const float*)d_in[0];
    const float* w_ih0 = (const float*)d_in[1];
    const float* w_hh0 = (const float*)d_in[2];
    const float* b_ih0 = (const float*)d_in[3];
    const float* b_hh0 = (const float*)d_in[4];
    const float* w_ih1 = (const float*)d_in[5];
    const float* w_hh1 = (const float*)d_in[6];
    const float* b_ih1 = (const float*)d_in[7];
    const float* b_hh1 = (const float*)d_in[8];
    const float* wq = (const float*)d_in[9];
    const float* bq = (const float*)d_in[10];
    const float* wk = (const float*)d_in[11];
    const float* bk = (const float*)d_in[12];
    const float* wv = (const float*)d_in[13];
    const float* bv = (const float*)d_in[14];
    const float* wo = (const float*)d_in[15];
    const float* bo = (const float*)d_in[16];
    const float* wm = (const float*)d_in[17];
    const float* bm = (const float*)d_in[18];
    const float* wvar = (const float*)d_in[19];
    const float* bvar = (const float*)d_in[20];
    float* out = (float*)d_out;

    dim3 grid_lstm(NC, B);   // 128 plain CTAs <= 148 SMs: co-resident, spin-safe
    fill_kernel<<<4096, 256>>>();                                        // #1
    xproj_kernel<<<dim3(S / 8, B), 256>>>(x, w_ih0, b_ih0, b_hh0);       // #2
    dummy_kernel<<<1, 32>>>();                                           // #3
    lstm0_kernel<<<grid_lstm, NT>>>(w_hh0);                              // #4 (profiled)
    lstm1_kernel<<<grid_lstm, NT>>>(w_ih1, w_hh1, b_ih1, b_hh1);         // #5
    attn_part_kernel<<<dim3(NSPLIT, B * 4), NT>>>(wq, bq, wk, bk);       // #6
    tail_kernel<<<B, NT>>>(wv, bv, wo, bo, wm, bm, wvar, bvar, out);     // #7
}

// round 17
// speedup vs baseline: 1.6195x; 1.6195x over previous
#include <cuda_runtime.h>
#include <math.h>
#include <stdint.h>

#define B 8
#define S 2048
#define I_IN 8
#define H 256
#define NC 16        // CTAs per batch
#define CHUNK 16     // h outputs per CTA
#define NT 256
#define NSPLIT 8
#define SC (S / NSPLIT)   // 256
#define CANARY 0x7FC00001u
#define GROWS (4 * H)     // 1024 gate rows

// ---------------- device scratch ----------------
__device__ float g_hs0[(size_t)B * S * H];
__device__ float g_hs1[(size_t)B * S * H];
__device__ float g_xp [(size_t)B * S * GROWS];   // w_ih0.x + b_ih0 + b_hh0
__device__ float g_pm[B * 4 * NSPLIT];
__device__ float g_ps[B * 4 * NSPLIT];
__device__ float g_ph[B * 4 * NSPLIT * H];
__device__ float g_attnc[B * H];

// HW tanh (sm_75+)
__device__ __forceinline__ float ftanh_(float x) {
    float y; asm("tanh.approx.f32 %0, %1;" : "=f"(y) : "f"(x)); return y;
}
__device__ __forceinline__ float fsig_(float x) {
    return 0.5f * ftanh_(0.5f * x) + 0.5f;
}

__device__ __forceinline__ uint64_t fma2_(uint64_t a, uint64_t b, uint64_t c) {
    uint64_t d;
    asm("fma.rn.f32x2 %0, %1, %2, %3;" : "=l"(d) : "l"(a), "l"(b), "l"(c));
    return d;
}
__device__ __forceinline__ float hsum2_(uint64_t v) {
    return __uint_as_float((uint32_t)v) + __uint_as_float((uint32_t)(v >> 32));
}
__device__ __forceinline__ uint32_t ldg_relaxed_u32(const uint32_t* p) {
    uint32_t v;
    asm volatile("ld.relaxed.gpu.global.b32 %0, [%1];" : "=r"(v) : "l"(p) : "memory");
    return v;
}
__device__ __forceinline__ void stg_relaxed_u32(uint32_t* p, uint32_t v) {
    asm volatile("st.relaxed.gpu.global.b32 [%0], %1;" :: "l"(p), "r"(v) : "memory");
}

// dependent-FMA delay (lat 4 per FMA); used only to phase-offset poll slots
__device__ __forceinline__ float delay_fma_(float x, int n) {
#pragma unroll
    for (int i = 0; i < n; i++)
        asm volatile("fma.rn.f32 %0, %0, 0f3F800001, 0f00000001;" : "+f"(x));
    return x;
}

// staggered 4-slot poll: 4 outstanding loads of the same word, phase-offset
// ~64 cyc. Sampling period ~64 cyc instead of the ~250-cyc dependent-loop.
__device__ __forceinline__ float poll_word_(const uint32_t* p) {
    uint32_t v = ldg_relaxed_u32(p);
    if (v != CANARY) return __uint_as_float(v);     // fast path
    uint32_t s0, s1, s2, s3;
    float d = 1.0f;
    s0 = ldg_relaxed_u32(p);
    d = delay_fma_(d, 16);                          // ~64 cyc
    s1 = ldg_relaxed_u32(p);
    d = delay_fma_(d, 16);
    s2 = ldg_relaxed_u32(p);
    d = delay_fma_(d, 16);
    s3 = ldg_relaxed_u32(p);
    // keep the delay chain alive (never true: CANARY is a NaN pattern != 1e-45)
    if (__float_as_uint(d) == 0x7F800000u) return d;
    while (true) {
        if (s0 != CANARY) return __uint_as_float(s0);
        s0 = ldg_relaxed_u32(p);
        if (s1 != CANARY) return __uint_as_float(s1);
        s1 = ldg_relaxed_u32(p);
        if (s2 != CANARY) return __uint_as_float(s2);
        s2 = ldg_relaxed_u32(p);
        if (s3 != CANARY) return __uint_as_float(s3);
        s3 = ldg_relaxed_u32(p);
    }
}

// ---------------- canary fill -----------------------------------------------------
__global__ void fill_kernel() {
    const uint4 c = make_uint4(CANARY, CANARY, CANARY, CANARY);
    const size_t n4 = (size_t)B * S * H / 4;
    uint4* p0 = reinterpret_cast<uint4*>(g_hs0);
    uint4* p1 = reinterpret_cast<uint4*>(g_hs1);
    for (size_t i = (size_t)blockIdx.x * blockDim.x + threadIdx.x; i < n4;
         i += (size_t)gridDim.x * blockDim.x) {
        p0[i] = c; p1[i] = c;
    }
}

// ---------------- x-projection precompute: xp = w_ih0 . x + b_ih0 + b_hh0 --------
__global__ void __launch_bounds__(256, 4) xproj_kernel(
    const float* __restrict__ xin, const float* __restrict__ w_ih0,
    const float* __restrict__ b_ih0, const float* __restrict__ b_hh0)
{
    const int t0 = blockIdx.x * 8;
    const int b  = blockIdx.y;
    const int tid = threadIdx.x;
    __shared__ float sx[8][I_IN];
    if (tid < 64) sx[tid >> 3][tid & 7] = xin[((size_t)b * S + t0 + (tid >> 3)) * I_IN + (tid & 7)];
    __syncthreads();
    float* xpb = g_xp + (size_t)b * S * GROWS;
#pragma unroll
    for (int rr = 0; rr < 4; rr++) {
        int row = rr * 256 + tid;
        float4 w0 = reinterpret_cast<const float4*>(w_ih0 + row * I_IN)[0];
        float4 w1 = reinterpret_cast<const float4*>(w_ih0 + row * I_IN)[1];
        float bias = b_ih0[row] + b_hh0[row];
#pragma unroll
        for (int ts = 0; ts < 8; ts++) {
            float v = bias
                + w0.x * sx[ts][0] + w0.y * sx[ts][1] + w0.z * sx[ts][2] + w0.w * sx[ts][3]
                + w1.x * sx[ts][4] + w1.y * sx[ts][5] + w1.z * sx[ts][6] + w1.w * sx[ts][7];
            xpb[(size_t)(t0 + ts) * GROWS + row] = v;
        }
    }
}

__global__ void dummy_kernel() {}

// ---------------- layer-0 LSTM (R12 structure + xp + staggered poll) -------------
__global__ void __launch_bounds__(NT, 1) lstm0_kernel(const float* __restrict__ w_hh0)
{
    const int r   = blockIdx.x;
    const int b   = blockIdx.y;
    const int tid = threadIdx.x;
    const int s   = tid >> 6;          // 64-wide segment of the 256-dot
    const int gL  = tid & 63;
    const int q   = gL >> 4;
    const int j   = gL & 15;
    const int row = q * H + r * CHUNK + j;

    __shared__ alignas(16) float sh_h[H];
    __shared__ float sh_part[4 * 64];

    uint64_t whh2[32];
    {
        const uint64_t* p = reinterpret_cast<const uint64_t*>(w_hh0) + ((row * H + s * 64) >> 1);
#pragma unroll
        for (int k = 0; k < 32; k++) whh2[k] = p[k];
    }

    uint32_t* hs_u = reinterpret_cast<uint32_t*>(g_hs0) + (size_t)b * S * H;

    const float* xp_base = g_xp + (size_t)b * S * GROWS + r * CHUNK;
    float xp[4];
    if (tid < CHUNK) {
#pragma unroll
        for (int qq = 0; qq < 4; qq++) xp[qq] = __ldg(xp_base + qq * H + tid);
    }

    sh_h[tid] = 0.f;
    __syncthreads();

    const bool self_word = (tid >= r * CHUNK) && (tid < r * CHUNK + CHUNK);
    float c = 0.f;   // cell state (owners tid<16)

    for (int t = 0; t < S; t++) {
        if (t > 0 && !self_word)
            sh_h[tid] = poll_word_(hs_u + (size_t)(t - 1) * H + tid);
        __syncthreads();                                   // S1

        const uint4* h128 = reinterpret_cast<const uint4*>(&sh_h[s * 64]);
        uint64_t a0 = 0, a1 = 0;
#pragma unroll
        for (int k = 0; k < 16; k++) {
            uint4 hv = h128[k];
            uint64_t lo = ((uint64_t)hv.y << 32) | hv.x;
            uint64_t hi = ((uint64_t)hv.w << 32) | hv.z;
            a0 = fma2_(whh2[2 * k], lo, a0);
            a1 = fma2_(whh2[2 * k + 1], hi, a1);
        }
        sh_part[s * 64 + gL] = hsum2_(a0) + hsum2_(a1);
        __syncthreads();                                   // S2

        if (tid < CHUNK) {
            float gate[4];
#pragma unroll
            for (int qq = 0; qq < 4; qq++) {
                int gg = qq * CHUNK + tid;
                gate[qq] = sh_part[gg] + sh_part[64 + gg] + sh_part[128 + gg]
                         + sh_part[192 + gg] + xp[qq];
            }
            float ig = fsig_(gate[0]);
            float fg = fsig_(gate[1]);
            float gv = ftanh_(gate[2]);
            float og = fsig_(gate[3]);
            c = fg * c + ig * gv;
            float hnew = og * ftanh_(c);
            sh_h[r * CHUNK + tid] = hnew;                  // self-seed
            stg_relaxed_u32(hs_u + (size_t)t * H + r * CHUNK + tid,
                            __float_as_uint(hnew));
            if (t + 1 < S) {
#pragma unroll
                for (int qq = 0; qq < 4; qq++)
                    xp[qq] = __ldg(xp_base + (size_t)(t + 1) * GROWS + qq * H + tid);
            }
        }
    }
}

// ---------------- layer-1 LSTM (R12 structure + staggered poll) -------------------
__global__ void __launch_bounds__(NT, 1) lstm1_kernel(
    const float* __restrict__ w_ih1, const float* __restrict__ w_hh1,
    const float* __restrict__ b_ih1, const float* __restrict__ b_hh1)
{
    const int r   = blockIdx.x;
    const int b   = blockIdx.y;
    const int tid = threadIdx.x;
    const int s   = tid >> 6;
    const int gL  = tid & 63;
    const int q   = gL >> 4;
    const int j   = gL & 15;
    const int row = q * H + r * CHUNK + j;

    __shared__ alignas(16) float sh_h[H];
    __shared__ alignas(16) float sh_x[H];
    __shared__ float sh_part[4 * 64];

    uint64_t whh2[32], wih2[32];
    {
        const uint64_t* p = reinterpret_cast<const uint64_t*>(w_hh1) + ((row * H + s * 64) >> 1);
#pragma unroll
        for (int k = 0; k < 32; k++) whh2[k] = p[k];
    }
    {
        const uint64_t* p = reinterpret_cast<const uint64_t*>(w_ih1) + ((row * H + s * 64) >> 1);
#pragma unroll
        for (int k = 0; k < 32; k++) wih2[k] = p[k];
    }

    float bias_q[4];
    if (tid < CHUNK) {
#pragma unroll
        for (int qq = 0; qq < 4; qq++) {
            int rr = qq * H + r * CHUNK + tid;
            bias_q[qq] = b_ih1[rr] + b_hh1[rr];
        }
    }

    const float* xb = g_hs0 + (size_t)b * S * H;           // complete at launch
    uint32_t* hs_u  = reinterpret_cast<uint32_t*>(g_hs1) + (size_t)b * S * H;

    sh_h[tid] = 0.f;
    float xreg = __ldg(xb + tid);                           // h0(0)
    __syncthreads();

    const bool self_word = (tid >= r * CHUNK) && (tid < r * CHUNK + CHUNK);
    float c = 0.f;

    for (int t = 0; t < S; t++) {
        sh_x[tid] = xreg;
        {
            int tn = (t + 1 < S) ? t + 1 : t;
            xreg = __ldg(xb + (size_t)tn * H + tid);
        }
        if (t > 0 && !self_word)
            sh_h[tid] = poll_word_(hs_u + (size_t)(t - 1) * H + tid);
        __syncthreads();                                   // S1

        const uint4* h128 = reinterpret_cast<const uint4*>(&sh_h[s * 64]);
        const uint4* x128 = reinterpret_cast<const uint4*>(&sh_x[s * 64]);
        uint64_t a0 = 0, a1 = 0;
#pragma unroll
        for (int k = 0; k < 16; k++) {
            uint4 hv = h128[k];
            uint64_t lo = ((uint64_t)hv.y << 32) | hv.x;
            uint64_t hi = ((uint64_t)hv.w << 32) | hv.z;
            a0 = fma2_(whh2[2 * k], lo, a0);
            a1 = fma2_(whh2[2 * k + 1], hi, a1);
        }
#pragma unroll
        for (int k = 0; k < 16; k++) {
            uint4 xv = x128[k];
            uint64_t lo = ((uint64_t)xv.y << 32) | xv.x;
            uint64_t hi = ((uint64_t)xv.w << 32) | xv.z;
            a0 = fma2_(wih2[2 * k], lo, a0);
            a1 = fma2_(wih2[2 * k + 1], hi, a1);
        }
        sh_part[s * 64 + gL] = hsum2_(a0) + hsum2_(a1);
        __syncthreads();                                   // S2

        if (tid < CHUNK) {
            float gate[4];
#pragma unroll
            for (int qq = 0; qq < 4; qq++) {
                int gg = qq * CHUNK + tid;
                gate[qq] = sh_part[gg] + sh_part[64 + gg] + sh_part[128 + gg]
                         + sh_part[192 + gg] + bias_q[qq];
            }
            float ig = fsig_(gate[0]);
            float fg = fsig_(gate[1]);
            float gv = ftanh_(gate[2]);
            float og = fsig_(gate[3]);
            c = fg * c + ig * gv;
            float hnew = og * ftanh_(c);
            sh_h[r * CHUNK + tid] = hnew;
            stg_relaxed_u32(hs_u + (size_t)t * H + r * CHUNK + tid,
                            __float_as_uint(hnew));
        }
    }
}

// ---------------- attention partials: split-S, split-softmax ---------------------
__global__ void __launch_bounds__(NT, 1) attn_part_kernel(
    const float* __restrict__ wq, const float* __restrict__ bq,
    const float* __restrict__ wk, const float* __restrict__ bk)
{
    const int cidx = blockIdx.x;
    const int bh   = blockIdx.y;
    const int b = bh >> 2, hd = bh & 3;
    const int tid = threadIdx.x;
    const float* h1b = g_hs1 + (size_t)b * S * H;
    const int base = cidx * SC;

    __shared__ float sh_last[H];
    __shared__ float sh_q[64];
    __shared__ float sh_qW[H];
    __shared__ float sh_qb;
    __shared__ float sc[SC];
    __shared__ float red[NT];

    sh_last[tid] = h1b[(size_t)(S - 1) * H + tid];
    __syncthreads();
    if (tid < 64) {
        int rq = hd * 64 + tid;
        float a = bq[rq];
#pragma unroll 4
        for (int k = 0; k < H; k++) a += wq[rq * H + k] * sh_last[k];
        sh_q[tid] = a;
    }
    __syncthreads();
    {
        float a = 0.f;
#pragma unroll 4
        for (int d = 0; d < 64; d++) a += sh_q[d] * wk[(hd * 64 + d) * H + tid];
        sh_qW[tid] = a;
    }
    if (tid == 0) {
        float a = 0.f;
        for (int d = 0; d < 64; d++) a += sh_q[d] * bk[hd * 64 + d];
        sh_qb = a;
    }
    __syncthreads();

    const float L2D = -0.07400058144377693f;   // log2(0.95)
    const int warp = tid >> 5, lane = tid & 31;
    float qr[8];
#pragma unroll
    for (int k = 0; k < 8; k++) qr[k] = sh_qW[lane * 8 + k];

#pragma unroll 2
    for (int i = warp; i < SC; i += 8) {
        int t = base + i;
        const float4* hr4 = reinterpret_cast<const float4*>(h1b + (size_t)t * H);
        float4 h0v = hr4[lane * 2], h1v = hr4[lane * 2 + 1];
        float a = qr[0]*h0v.x + qr[1]*h0v.y + qr[2]*h0v.z + qr[3]*h0v.w
                + qr[4]*h1v.x + qr[5]*h1v.y + qr[6]*h1v.z + qr[7]*h1v.w;
#pragma unroll
        for (int o = 16; o; o >>= 1) a += __shfl_xor_sync(0xffffffffu, a, o);
        if (lane == 0)
            sc[i] = (a + sh_qb) * 0.125f * exp2f((float)(S - 1 - t) * L2D);
    }
    __syncthreads();

    red[tid] = sc[tid]; __syncthreads();
    for (int o = NT / 2; o; o >>= 1) { if (tid < o) red[tid] = fmaxf(red[tid], red[tid + o]); __syncthreads(); }
    const float M = red[0]; __syncthreads();
    float e = expf(sc[tid] - M);
    sc[tid] = e;
    red[tid] = e; __syncthreads();
    for (int o = NT / 2; o; o >>= 1) { if (tid < o) red[tid] += red[tid + o]; __syncthreads(); }
    const float SUM = red[0];
    __syncthreads();

    float acc = 0.f;
#pragma unroll 8
    for (int i = 0; i < SC; i++) acc += sc[i] * h1b[(size_t)(base + i) * H + tid];
    g_ph[(size_t)(bh * NSPLIT + cidx) * H + tid] = acc;
    if (tid == 0) { g_pm[bh * NSPLIT + cidx] = M; g_ps[bh * NSPLIT + cidx] = SUM; }
}

// ---------------- combine splits + V projection (grid = 32 bh) --------------------
__global__ void __launch_bounds__(NT, 1) attn_combine_kernel(
    const float* __restrict__ wv, const float* __restrict__ bv)
{
    const int bh = blockIdx.x;
    const int b = bh >> 2, hd = bh & 3;
    const int tid = threadIdx.x;
    __shared__ float sh_w[NSPLIT];
    __shared__ float sh_hbar[H];
    __shared__ float sh_inv;
    if (tid == 0) {
        float M = -1e30f;
        for (int cI = 0; cI < NSPLIT; cI++) M = fmaxf(M, g_pm[bh * NSPLIT + cI]);
        float tot = 0.f;
        for (int cI = 0; cI < NSPLIT; cI++) {
            float w = expf(g_pm[bh * NSPLIT + cI] - M);
            sh_w[cI] = w;
            tot += w * g_ps[bh * NSPLIT + cI];
        }
        sh_inv = 1.f / tot;
    }
    __syncthreads();
    float a = 0.f;
#pragma unroll
    for (int cI = 0; cI < NSPLIT; cI++) a += sh_w[cI] * g_ph[(size_t)(bh * NSPLIT + cI) * H + tid];
    sh_hbar[tid] = a * sh_inv;
    __syncthreads();
    if (tid < 64) {
        int rv = hd * 64 + tid;
        float o = bv[rv];
#pragma unroll 4
        for (int k = 0; k < H; k++) o += wv[rv * H + k] * sh_hbar[k];
        g_attnc[b * H + hd * 64 + tid] = o;
    }
}

// ---------------- output heads ----------------------------------------------------
__global__ void __launch_bounds__(NT, 1) head_kernel(
    const float* __restrict__ wo, const float* __restrict__ bo,
    const float* __restrict__ wm, const float* __restrict__ bm,
    const float* __restrict__ wvr, const float* __restrict__ bvr,
    float* __restrict__ out)
{
    const int b = blockIdx.x;
    const int tid = threadIdx.x;
    __shared__ float sa[H], sctx[H];
    sa[tid] = g_attnc[b * H + tid];
    __syncthreads();
    float a = bo[tid];
#pragma unroll 4
    for (int k = 0; k < H; k++) a += wo[tid * H + k] * sa[k];
    sctx[tid] = a;
    __syncthreads();
    if (tid < 5) {
        float m = bm[tid], lv = bvr[tid];
        for (int k = 0; k < H; k++) {
            m  += wm[tid * H + k] * sctx[k];
            lv += wvr[tid * H + k] * sctx[k];
        }
        out[b * 5 + tid] = m;
        out[B * 5 + b * 5 + tid] = lv;
    }
}

// ---------------- launch ----------------------------------------------------------
extern "C" void kernel_launch(void* const* d_in, const int* in_sizes, int n_in,
                              void* d_out, int out_size) {
    const float* x     = (const float*)d_in[0];
    const float* w_ih0 = (const float*)d_in[1];
    const float* w_hh0 = (const float*)d_in[2];
    const float* b_ih0 = (const float*)d_in[3];
    const float* b_hh0 = (const float*)d_in[4];
    const float* w_ih1 = (const float*)d_in[5];
    const float* w_hh1 = (const float*)d_in[6];
    const float* b_ih1 = (const float*)d_in[7];
    const float* b_hh1 = (const float*)d_in[8];
    const float* wq = (const float*)d_in[9];
    const float* bq = (const float*)d_in[10];
    const float* wk = (const float*)d_in[11];
    const float* bk = (const float*)d_in[12];
    const float* wv = (const float*)d_in[13];
    const float* bv = (const float*)d_in[14];
    const float* wo = (const float*)d_in[15];
    const float* bo = (const float*)d_in[16];
    const float* wm = (const float*)d_in[17];
    const float* bm = (const float*)d_in[18];
    const float* wvar = (const float*)d_in[19];
    const float* bvar = (const float*)d_in[20];
    float* out = (float*)d_out;

    dim3 grid_lstm(NC, B);   // 128 plain CTAs <= 148 SMs: co-resident, spin-safe
    fill_kernel<<<4096, 256>>>();                                        // #1
    xproj_kernel<<<dim3(S / 8, B), 256>>>(x, w_ih0, b_ih0, b_hh0);       // #2
    dummy_kernel<<<1, 32>>>();                                           // #3
    lstm0_kernel<<<grid_lstm, NT>>>(w_hh0);                              // #4 (profiled)
    lstm1_kernel<<<grid_lstm, NT>>>(w_ih1, w_hh1, b_ih1, b_hh1);         // #5
    attn_part_kernel<<<dim3(NSPLIT, B * 4), NT>>>(wq, bq, wk, bk);       // #6
    attn_combine_kernel<<<B * 4, NT>>>(wv, bv);                          // #7
    head_kernel<<<B, NT>>>(wo, bo, wm, bm, wvar, bvar, out);             // #8
}